// round 4
// baseline (speedup 1.0000x reference)
#include <cuda_runtime.h>
#include <math.h>
#include <stdint.h>

// Problem constants
#define BB 2
#define SS 4096
#define FF 768
#define HH 12
#define DD 64
#define MM (BB * SS)       // 8192 rows
#define NQKV (3 * FF)      // 2304

// Scratch (allocation-free rule: __device__ globals)
__device__ float g_qkv[(size_t)MM * NQKV];   // [B*S, 3F]  ~75.5 MB
__device__ float g_att[(size_t)MM * FF];     // [B*S, F]   ~25 MB

// ---------------------------------------------------------------------------
// GEMM + bias: C[M,N] = A[M,K] @ W[K,N] + bias[N]
// 128x128x16 block tile, 256 threads, 8x8 per-thread microtile.
// A tile stored k-major (transposed) with stride 132 so the a-fragment is a
// broadcast LDS.128; B tile natural with lane-consecutive LDS.128.
// All dims here are multiples of the tile sizes (8192 / {2304,768} / 768).
// ---------------------------------------------------------------------------
__global__ __launch_bounds__(256) void gemm_bias_kernel(
    const float* __restrict__ A, const float* __restrict__ W,
    const float* __restrict__ bias, float* __restrict__ C,
    int M, int N, int K)
{
    __shared__ float Ast[16 * 132];
    __shared__ float Bsh[16 * 128];

    const int tid = threadIdx.x;
    const int ty = tid >> 4;       // 0..15
    const int tx = tid & 15;       // 0..15
    const int row0 = blockIdx.y * 128;
    const int col0 = blockIdx.x * 128;

    float acc[8][8];
#pragma unroll
    for (int i = 0; i < 8; i++)
#pragma unroll
        for (int j = 0; j < 8; j++) acc[i][j] = 0.f;

    for (int k0 = 0; k0 < K; k0 += 16) {
#pragma unroll
        for (int l = 0; l < 2; l++) {
            int f4 = tid + l * 256;
            // A: 128 rows x 16 cols = 512 float4
            int ar = f4 >> 2, ac = f4 & 3;
            float4 av = *(const float4*)(A + (size_t)(row0 + ar) * K + k0 + ac * 4);
            Ast[(ac * 4 + 0) * 132 + ar] = av.x;
            Ast[(ac * 4 + 1) * 132 + ar] = av.y;
            Ast[(ac * 4 + 2) * 132 + ar] = av.z;
            Ast[(ac * 4 + 3) * 132 + ar] = av.w;
            // B: 16 rows x 128 cols = 512 float4
            int br = f4 >> 5, bc = f4 & 31;
            *(float4*)(Bsh + br * 128 + bc * 4) =
                *(const float4*)(W + (size_t)(k0 + br) * N + col0 + bc * 4);
        }
        __syncthreads();

#pragma unroll
        for (int kk = 0; kk < 16; kk++) {
            float a[8], b[8];
            *(float4*)(a)     = *(const float4*)(Ast + kk * 132 + ty * 8);
            *(float4*)(a + 4) = *(const float4*)(Ast + kk * 132 + ty * 8 + 4);
            *(float4*)(b)     = *(const float4*)(Bsh + kk * 128 + tx * 8);
            *(float4*)(b + 4) = *(const float4*)(Bsh + kk * 128 + tx * 8 + 4);
#pragma unroll
            for (int i = 0; i < 8; i++)
#pragma unroll
                for (int j = 0; j < 8; j++)
                    acc[i][j] += a[i] * b[j];
        }
        __syncthreads();
    }

#pragma unroll
    for (int i = 0; i < 8; i++) {
        int r = row0 + ty * 8 + i;
#pragma unroll
        for (int g = 0; g < 2; g++) {
            int c = col0 + tx * 8 + g * 4;
            float4 o;
            o.x = acc[i][g * 4 + 0] + bias[c + 0];
            o.y = acc[i][g * 4 + 1] + bias[c + 1];
            o.z = acc[i][g * 4 + 2] + bias[c + 2];
            o.w = acc[i][g * 4 + 3] + bias[c + 3];
            *(float4*)(C + (size_t)r * N + c) = o;
        }
    }
}

// ---------------------------------------------------------------------------
// Flash attention (causal + key padding mask), fp32.
// One CTA = one (b, h, 64-query block). 256 threads, 4x4 microtiles.
// Qt/Kt stored d-major [64][68]; Vs k-major [64][68]; P written transposed
// Pt[k][q] so the P@V pass reads broadcast a-fragments. Stride 68 keeps all
// LDS.128 16B-aligned and the Pt scalar stores conflict-light.
// Dynamic smem: 4 * 64*68*4 = 69632 B.
// ---------------------------------------------------------------------------
__global__ __launch_bounds__(256) void attn_kernel(
    const float* __restrict__ qkv, const unsigned char* __restrict__ mask,
    float* __restrict__ att)
{
    extern __shared__ float sm[];
    float* Qt = sm;                 // [d=64][q=64] stride 68
    float* Kt = sm + 64 * 68;       // [d=64][k=64] stride 68
    float* Vs = sm + 2 * 64 * 68;   // [k=64][d=64] stride 68
    float* Pt = sm + 3 * 64 * 68;   // [k=64][q=64] stride 68

    const int qb = blockIdx.x;
    const int h  = blockIdx.y;
    const int b  = blockIdx.z;
    const int tid = threadIdx.x;
    const int ty = tid >> 4;
    const int tx = tid & 15;
    const int q0 = qb * 64;
    const size_t rowbase = (size_t)b * SS;

    // Load Q tile, transposed + pre-scaled by 1/sqrt(D)
#pragma unroll
    for (int l = 0; l < 4; l++) {
        int f4 = tid + l * 256;            // 0..1023
        int r = f4 >> 4;                   // q row 0..63
        int c = f4 & 15;                   // d/4
        float4 v = *(const float4*)(qkv + (rowbase + q0 + r) * NQKV + h * DD + c * 4);
        Qt[(c * 4 + 0) * 68 + r] = v.x * 0.125f;
        Qt[(c * 4 + 1) * 68 + r] = v.y * 0.125f;
        Qt[(c * 4 + 2) * 68 + r] = v.z * 0.125f;
        Qt[(c * 4 + 3) * 68 + r] = v.w * 0.125f;
    }

    float m_i[4], l_i[4], acc[4][4];
#pragma unroll
    for (int i = 0; i < 4; i++) {
        m_i[i] = -INFINITY;
        l_i[i] = 0.f;
#pragma unroll
        for (int j = 0; j < 4; j++) acc[i][j] = 0.f;
    }

    for (int kb = 0; kb <= qb; kb++) {
        const int k0 = kb * 64;
        __syncthreads();  // prev iter done with Kt/Vs/Pt; also publishes Qt on iter 0

        // Load K (transposed) and V tiles
#pragma unroll
        for (int l = 0; l < 4; l++) {
            int f4 = tid + l * 256;
            int r = f4 >> 4;               // k row
            int c = f4 & 15;               // d/4
            const float* kp = qkv + (rowbase + k0 + r) * NQKV + FF + h * DD + c * 4;
            float4 kv = *(const float4*)kp;
            Kt[(c * 4 + 0) * 68 + r] = kv.x;
            Kt[(c * 4 + 1) * 68 + r] = kv.y;
            Kt[(c * 4 + 2) * 68 + r] = kv.z;
            Kt[(c * 4 + 3) * 68 + r] = kv.w;
            *(float4*)(Vs + r * 68 + c * 4) = *(const float4*)(kp + FF);  // V is K + F
        }
        __syncthreads();

        // S = (Q/sqrt(D)) @ K^T  -- contraction over d
        float s[4][4];
#pragma unroll
        for (int i = 0; i < 4; i++)
#pragma unroll
            for (int j = 0; j < 4; j++) s[i][j] = 0.f;
#pragma unroll 8
        for (int kk = 0; kk < 64; kk++) {
            float a[4], bv[4];
            *(float4*)a  = *(const float4*)(Qt + kk * 68 + ty * 4);
            *(float4*)bv = *(const float4*)(Kt + kk * 68 + tx * 4);
#pragma unroll
            for (int i = 0; i < 4; i++)
#pragma unroll
                for (int j = 0; j < 4; j++)
                    s[i][j] += a[i] * bv[j];
        }

        // Masks: causal on the diagonal block, padding on keys
        uchar4 pmv = *(const uchar4*)(mask + (size_t)b * SS + k0 + tx * 4);
        unsigned char pm[4] = {pmv.x, pmv.y, pmv.z, pmv.w};
        const bool diag = (kb == qb);
#pragma unroll
        for (int j = 0; j < 4; j++) {
            int kidx = k0 + tx * 4 + j;
#pragma unroll
            for (int i = 0; i < 4; i++) {
                int qidx = q0 + ty * 4 + i;
                if (pm[j] || (diag && kidx > qidx)) s[i][j] = -INFINITY;
            }
        }

        // Online softmax (row stats shared across the 16 tx lanes via shfl)
#pragma unroll
        for (int i = 0; i < 4; i++) {
            float rmax = fmaxf(fmaxf(s[i][0], s[i][1]), fmaxf(s[i][2], s[i][3]));
#pragma unroll
            for (int off = 1; off < 16; off <<= 1)
                rmax = fmaxf(rmax, __shfl_xor_sync(0xffffffffu, rmax, off));
            float mnew = fmaxf(m_i[i], rmax);
            float alpha = __expf(m_i[i] - mnew);   // 0 on first block (m=-inf)
            m_i[i] = mnew;
            float rsum = 0.f;
#pragma unroll
            for (int j = 0; j < 4; j++) {
                float p = __expf(s[i][j] - mnew);
                s[i][j] = p;
                rsum += p;
            }
#pragma unroll
            for (int off = 1; off < 16; off <<= 1)
                rsum += __shfl_xor_sync(0xffffffffu, rsum, off);
            l_i[i] = l_i[i] * alpha + rsum;
#pragma unroll
            for (int j = 0; j < 4; j++) acc[i][j] *= alpha;
        }

        // Publish P transposed: Pt[k][q]
#pragma unroll
        for (int j = 0; j < 4; j++)
#pragma unroll
            for (int i = 0; i < 4; i++)
                Pt[(tx * 4 + j) * 68 + (ty * 4 + i)] = s[i][j];
        __syncthreads();

        // O += P @ V  -- contraction over k
#pragma unroll 8
        for (int kk = 0; kk < 64; kk++) {
            float a[4], bv[4];
            *(float4*)a  = *(const float4*)(Pt + kk * 68 + ty * 4);
            *(float4*)bv = *(const float4*)(Vs + kk * 68 + tx * 4);
#pragma unroll
            for (int i = 0; i < 4; i++)
#pragma unroll
                for (int j = 0; j < 4; j++)
                    acc[i][j] += a[i] * bv[j];
        }
    }

    // Epilogue: O / l, write [B*S, F] with column h*D + d
#pragma unroll
    for (int i = 0; i < 4; i++) {
        float inv = 1.f / l_i[i];
        float4 o;
        o.x = acc[i][0] * inv;
        o.y = acc[i][1] * inv;
        o.z = acc[i][2] * inv;
        o.w = acc[i][3] * inv;
        *(float4*)(att + (rowbase + q0 + ty * 4 + i) * FF + h * DD + tx * 4) = o;
    }
}

// ---------------------------------------------------------------------------
// Launch
// ---------------------------------------------------------------------------
extern "C" void kernel_launch(void* const* d_in, const int* in_sizes, int n_in,
                              void* d_out, int out_size)
{
    (void)in_sizes; (void)n_in; (void)out_size;
    const float*         x    = (const float*)d_in[0];
    const unsigned char* mask = (const unsigned char*)d_in[1];  // bool keys
    const float*         Wqkv = (const float*)d_in[2];
    const float*         bqkv = (const float*)d_in[3];
    const float*         Wout = (const float*)d_in[4];
    const float*         bout = (const float*)d_in[5];
    float*               out  = (float*)d_out;

    void* p;
    cudaGetSymbolAddress(&p, g_qkv);
    float* qkv = (float*)p;
    cudaGetSymbolAddress(&p, g_att);
    float* att = (float*)p;

    // 1) QKV projection: [8192,768] @ [768,2304] + bias
    dim3 g1(NQKV / 128, MM / 128);  // (18, 64)
    gemm_bias_kernel<<<g1, 256>>>(x, Wqkv, bqkv, qkv, MM, NQKV, FF);

    // 2) Causal flash attention
    const int smem = 4 * 64 * 68 * (int)sizeof(float);  // 69632 B
    cudaFuncSetAttribute(attn_kernel, cudaFuncAttributeMaxDynamicSharedMemorySize, smem);
    attn_kernel<<<dim3(SS / 64, HH, BB), 256, smem>>>(qkv, mask, att);

    // 3) Output projection: [8192,768] @ [768,768] + bias
    dim3 g2(FF / 128, MM / 128);    // (6, 64)
    gemm_bias_kernel<<<g2, 256>>>(att, Wout, bout, out, MM, FF, FF);
}

// round 7
// speedup vs baseline: 2.2960x; 2.2960x over previous
#include <cuda_runtime.h>
#include <math.h>
#include <stdint.h>

// Problem constants
#define BB 2
#define SS 4096
#define FF 768
#define HH 12
#define DD 64
#define MM (BB * SS)       // 8192
#define NQKV (3 * FF)      // 2304

// Scratch (allocation-free rule: __device__ globals)
__device__ float g_qkv[(size_t)MM * NQKV];   // [B*S, 3F]
__device__ float g_att[(size_t)MM * FF];     // [B*S, F]

// ---------------------------------------------------------------------------
// tf32 helpers. cvt.rna (round-to-nearest) is REQUIRED: bit-truncation to tf32
// is biased toward zero and the bias accumulates linearly over K.
// ---------------------------------------------------------------------------
__device__ __forceinline__ unsigned f2tf(float x) {
    unsigned u;
    asm("cvt.rna.tf32.f32 %0, %1;" : "=r"(u) : "f"(x));
    return u;
}
__device__ __forceinline__ float f2tff(float x) { return __uint_as_float(f2tf(x)); }

// D(16x8) += A(16x8,row) * B(8x8,col), tf32 inputs, fp32 accum.
__device__ __forceinline__ void mma8(float d[4], const unsigned a[4],
                                     unsigned b0, unsigned b1) {
    asm volatile(
        "mma.sync.aligned.m16n8k8.row.col.f32.tf32.tf32.f32 "
        "{%0,%1,%2,%3},{%4,%5,%6,%7},{%8,%9},{%0,%1,%2,%3};"
        : "+f"(d[0]), "+f"(d[1]), "+f"(d[2]), "+f"(d[3])
        : "r"(a[0]), "r"(a[1]), "r"(a[2]), "r"(a[3]), "r"(b0), "r"(b1));
}

// ---------------------------------------------------------------------------
// GEMM + bias, tf32 tensor-core: C[M,N] = A[M,K] @ W[K,N] + bias[N]
// 128x128 CTA tile, 8 warps (4m x 2n), warp tile 32x64, k-chunk 16.
// As stride 20, Bs stride 136: fragment LDS patterns (8 rows x 4 cols) hit
// all 32 banks -> conflict-free.
// ---------------------------------------------------------------------------
#define AST 20
#define BST 136
__global__ __launch_bounds__(256) void gemm_tf32_kernel(
    const float* __restrict__ A, const float* __restrict__ W,
    const float* __restrict__ bias, float* __restrict__ C,
    int M, int N, int K)
{
    __shared__ float As[128 * AST];   // [m][k] tf32-rounded
    __shared__ float Bs[16 * BST];    // [k][n] tf32-rounded

    const int tid = threadIdx.x;
    const int wid = tid >> 5, lane = tid & 31;
    const int g = lane >> 2, tig = lane & 3;
    const int wm = (wid >> 1) * 32;   // warp m offset (0,32,64,96)
    const int wn = (wid & 1) * 64;    // warp n offset (0,64)
    const int row0 = blockIdx.y * 128;
    const int col0 = blockIdx.x * 128;

    float acc[2][8][4];
#pragma unroll
    for (int mt = 0; mt < 2; mt++)
#pragma unroll
        for (int nt = 0; nt < 8; nt++)
#pragma unroll
            for (int c = 0; c < 4; c++) acc[mt][nt][c] = 0.f;

    for (int k0 = 0; k0 < K; k0 += 16) {
#pragma unroll
        for (int l = 0; l < 2; l++) {
            int id = tid + l * 256;           // 0..511
            // A: 128 rows x 16 k
            int ar = id >> 2, ac = id & 3;
            float4 av = *(const float4*)(A + (size_t)(row0 + ar) * K + k0 + ac * 4);
            float4 at;
            at.x = f2tff(av.x); at.y = f2tff(av.y);
            at.z = f2tff(av.z); at.w = f2tff(av.w);
            *(float4*)(As + ar * AST + ac * 4) = at;
            // B: 16 k x 128 n
            int br = id >> 5, bc = id & 31;
            float4 bv = *(const float4*)(W + (size_t)(k0 + br) * N + col0 + bc * 4);
            float4 bt;
            bt.x = f2tff(bv.x); bt.y = f2tff(bv.y);
            bt.z = f2tff(bv.z); bt.w = f2tff(bv.w);
            *(float4*)(Bs + br * BST + bc * 4) = bt;
        }
        __syncthreads();

#pragma unroll
        for (int ks = 0; ks < 16; ks += 8) {
            unsigned a[2][4];
#pragma unroll
            for (int mt = 0; mt < 2; mt++) {
                int rbse = wm + mt * 16;
                a[mt][0] = __float_as_uint(As[(rbse + g) * AST + ks + tig]);
                a[mt][1] = __float_as_uint(As[(rbse + g + 8) * AST + ks + tig]);
                a[mt][2] = __float_as_uint(As[(rbse + g) * AST + ks + tig + 4]);
                a[mt][3] = __float_as_uint(As[(rbse + g + 8) * AST + ks + tig + 4]);
            }
#pragma unroll
            for (int nt = 0; nt < 8; nt++) {
                unsigned b0 = __float_as_uint(Bs[(ks + tig) * BST + wn + nt * 8 + g]);
                unsigned b1 = __float_as_uint(Bs[(ks + tig + 4) * BST + wn + nt * 8 + g]);
                mma8(acc[0][nt], a[0], b0, b1);
                mma8(acc[1][nt], a[1], b0, b1);
            }
        }
        __syncthreads();
    }

#pragma unroll
    for (int mt = 0; mt < 2; mt++) {
        int r0 = row0 + wm + mt * 16 + g;
#pragma unroll
        for (int nt = 0; nt < 8; nt++) {
            int c = col0 + wn + nt * 8 + 2 * tig;
            float bx = bias[c], by = bias[c + 1];
            *(float2*)(C + (size_t)r0 * N + c) =
                make_float2(acc[mt][nt][0] + bx, acc[mt][nt][1] + by);
            *(float2*)(C + (size_t)(r0 + 8) * N + c) =
                make_float2(acc[mt][nt][2] + bx, acc[mt][nt][3] + by);
        }
    }
}

// ---------------------------------------------------------------------------
// Flash attention, tf32 tensor-core. 128-query x 64-key blocks, 8 warps,
// warp owns m16 x n64. Q fragments resident in registers. K[key][d] and
// Vt[d][key] (stride 68) give conflict-free B-fragment loads. P bounced
// through smem (tf32-rounded) between the QK and PV MMAs.
// Dynamic smem: (2*64*68 + 128*68)*4 + 64 = 69696 B.
// ---------------------------------------------------------------------------
__global__ __launch_bounds__(256, 1) void attn_tf32_kernel(
    const float* __restrict__ qkv, const unsigned char* __restrict__ mask,
    float* __restrict__ att)
{
    extern __shared__ float sm[];
    float* Ks = sm;                    // [64 key][68]  (d inner)
    float* Vt = sm + 64 * 68;          // [64 d][68]    (key inner)
    float* Ps = sm + 2 * 64 * 68;      // [128 q][68]   (key inner)
    unsigned char* msk = (unsigned char*)(sm + 2 * 64 * 68 + 128 * 68);

    const int qb = gridDim.x - 1 - blockIdx.x;   // big blocks first (balance)
    const int h = blockIdx.y, b = blockIdx.z;
    const int tid = threadIdx.x;
    const int wid = tid >> 5, lane = tid & 31;
    const int g = lane >> 2, tig = lane & 3;
    const int m0 = wid * 16;
    const int q0 = qb * 128;
    const size_t rb = (size_t)b * SS;
    const int qr0 = q0 + m0 + g;      // this thread's two query rows
    const int qr1 = qr0 + 8;

    // Q fragments (pre-scaled by 1/sqrt(D), tf32-rounded), resident all kernel
    unsigned qf[8][4];
    {
        const float* p0 = qkv + (rb + qr0) * NQKV + h * DD;
        const float* p1 = p0 + (size_t)8 * NQKV;
#pragma unroll
        for (int kk = 0; kk < 8; kk++) {
            qf[kk][0] = f2tf(p0[kk * 8 + tig] * 0.125f);
            qf[kk][1] = f2tf(p1[kk * 8 + tig] * 0.125f);
            qf[kk][2] = f2tf(p0[kk * 8 + tig + 4] * 0.125f);
            qf[kk][3] = f2tf(p1[kk * 8 + tig + 4] * 0.125f);
        }
    }

    float m_i[2] = {-INFINITY, -INFINITY};
    float l_i[2] = {0.f, 0.f};
    float oacc[8][4];
#pragma unroll
    for (int nt = 0; nt < 8; nt++)
#pragma unroll
        for (int c = 0; c < 4; c++) oacc[nt][c] = 0.f;

    const int nkb = 2 * qb + 2;
    for (int kb = 0; kb < nkb; kb++) {
        const int k0 = kb * 64;
        __syncthreads();   // previous iter done reading Ks/Vt/Ps

        // Load K (row-major, tf32) and V (transposed to [d][key], tf32)
#pragma unroll
        for (int l = 0; l < 4; l++) {
            int id = tid + l * 256;        // 0..1023
            int r = id >> 4, c = id & 15;  // key row, d/4
            const float* kp = qkv + (rb + k0 + r) * NQKV + FF + h * DD + c * 4;
            float4 kv = *(const float4*)kp;
            float4 kt;
            kt.x = f2tff(kv.x); kt.y = f2tff(kv.y);
            kt.z = f2tff(kv.z); kt.w = f2tff(kv.w);
            *(float4*)(Ks + r * 68 + c * 4) = kt;
            float4 vv = *(const float4*)(kp + FF);   // V = K + F
            Vt[(c * 4 + 0) * 68 + r] = f2tff(vv.x);
            Vt[(c * 4 + 1) * 68 + r] = f2tff(vv.y);
            Vt[(c * 4 + 2) * 68 + r] = f2tff(vv.z);
            Vt[(c * 4 + 3) * 68 + r] = f2tff(vv.w);
        }
        if (tid < 64) msk[tid] = mask[rb + k0 + tid];
        __syncthreads();

        // S = Q @ K^T  (contraction over d, 8 k-steps)
        float sacc[8][4];
#pragma unroll
        for (int nt = 0; nt < 8; nt++)
#pragma unroll
            for (int c = 0; c < 4; c++) sacc[nt][c] = 0.f;
#pragma unroll
        for (int kk = 0; kk < 8; kk++) {
#pragma unroll
            for (int nt = 0; nt < 8; nt++) {
                unsigned b0 = __float_as_uint(Ks[(nt * 8 + g) * 68 + kk * 8 + tig]);
                unsigned b1 = __float_as_uint(Ks[(nt * 8 + g) * 68 + kk * 8 + tig + 4]);
                mma8(sacc[nt], qf[kk], b0, b1);
            }
        }

        // Causal + padding masks
        const bool dcheck = (k0 + 63 > qr0);  // any causal masking possible here
#pragma unroll
        for (int nt = 0; nt < 8; nt++) {
            int c0 = k0 + nt * 8 + 2 * tig;
            bool p0 = msk[nt * 8 + 2 * tig] != 0;
            bool p1 = msk[nt * 8 + 2 * tig + 1] != 0;
            if (p0 || (dcheck && c0 > qr0))     sacc[nt][0] = -INFINITY;
            if (p1 || (dcheck && c0 + 1 > qr0)) sacc[nt][1] = -INFINITY;
            if (p0 || (dcheck && c0 > qr1))     sacc[nt][2] = -INFINITY;
            if (p1 || (dcheck && c0 + 1 > qr1)) sacc[nt][3] = -INFINITY;
        }

        // Online softmax: row r lives in this thread's quad (2 shfl_xor)
#pragma unroll
        for (int r = 0; r < 2; r++) {
            float mx = -INFINITY;
#pragma unroll
            for (int nt = 0; nt < 8; nt++)
                mx = fmaxf(mx, fmaxf(sacc[nt][2 * r], sacc[nt][2 * r + 1]));
            mx = fmaxf(mx, __shfl_xor_sync(0xffffffffu, mx, 1));
            mx = fmaxf(mx, __shfl_xor_sync(0xffffffffu, mx, 2));
            float mnew = fmaxf(m_i[r], mx);
            float alpha = __expf(m_i[r] - mnew);   // 0 on first block
            float sum = 0.f;
#pragma unroll
            for (int nt = 0; nt < 8; nt++) {
                float e0 = __expf(sacc[nt][2 * r] - mnew);
                float e1 = __expf(sacc[nt][2 * r + 1] - mnew);
                sacc[nt][2 * r] = e0;
                sacc[nt][2 * r + 1] = e1;
                sum += e0 + e1;
            }
            sum += __shfl_xor_sync(0xffffffffu, sum, 1);
            sum += __shfl_xor_sync(0xffffffffu, sum, 2);
            l_i[r] = l_i[r] * alpha + sum;
            m_i[r] = mnew;
#pragma unroll
            for (int nt = 0; nt < 8; nt++) {
                oacc[nt][2 * r] *= alpha;
                oacc[nt][2 * r + 1] *= alpha;
            }
        }

        // Publish P (tf32) for the PV MMA
#pragma unroll
        for (int nt = 0; nt < 8; nt++) {
            *(float2*)(Ps + (m0 + g) * 68 + nt * 8 + 2 * tig) =
                make_float2(f2tff(sacc[nt][0]), f2tff(sacc[nt][1]));
            *(float2*)(Ps + (m0 + g + 8) * 68 + nt * 8 + 2 * tig) =
                make_float2(f2tff(sacc[nt][2]), f2tff(sacc[nt][3]));
        }
        __syncthreads();

        // O += P @ V  (contraction over keys, 8 k-steps)
#pragma unroll
        for (int kk = 0; kk < 8; kk++) {
            unsigned a[4];
            a[0] = __float_as_uint(Ps[(m0 + g) * 68 + kk * 8 + tig]);
            a[1] = __float_as_uint(Ps[(m0 + g + 8) * 68 + kk * 8 + tig]);
            a[2] = __float_as_uint(Ps[(m0 + g) * 68 + kk * 8 + tig + 4]);
            a[3] = __float_as_uint(Ps[(m0 + g + 8) * 68 + kk * 8 + tig + 4]);
#pragma unroll
            for (int nt = 0; nt < 8; nt++) {
                unsigned b0 = __float_as_uint(Vt[(nt * 8 + g) * 68 + kk * 8 + tig]);
                unsigned b1 = __float_as_uint(Vt[(nt * 8 + g) * 68 + kk * 8 + tig + 4]);
                mma8(oacc[nt], a, b0, b1);
            }
        }
    }

    // Epilogue: O / l -> att[B*S, F]
    const float inv0 = 1.f / l_i[0];
    const float inv1 = 1.f / l_i[1];
#pragma unroll
    for (int nt = 0; nt < 8; nt++) {
        int c = h * DD + nt * 8 + 2 * tig;
        *(float2*)(att + (rb + qr0) * FF + c) =
            make_float2(oacc[nt][0] * inv0, oacc[nt][1] * inv0);
        *(float2*)(att + (rb + qr1) * FF + c) =
            make_float2(oacc[nt][2] * inv1, oacc[nt][3] * inv1);
    }
}

// ---------------------------------------------------------------------------
// Launch
// ---------------------------------------------------------------------------
extern "C" void kernel_launch(void* const* d_in, const int* in_sizes, int n_in,
                              void* d_out, int out_size)
{
    (void)in_sizes; (void)n_in; (void)out_size;
    const float*         x    = (const float*)d_in[0];
    const unsigned char* mask = (const unsigned char*)d_in[1];
    const float*         Wqkv = (const float*)d_in[2];
    const float*         bqkv = (const float*)d_in[3];
    const float*         Wout = (const float*)d_in[4];
    const float*         bout = (const float*)d_in[5];
    float*               out  = (float*)d_out;

    void* p;
    cudaGetSymbolAddress(&p, g_qkv);
    float* qkv = (float*)p;
    cudaGetSymbolAddress(&p, g_att);
    float* att = (float*)p;

    // 1) QKV projection
    dim3 g1(NQKV / 128, MM / 128);   // (18, 64)
    gemm_tf32_kernel<<<g1, 256>>>(x, Wqkv, bqkv, qkv, MM, NQKV, FF);

    // 2) Causal flash attention (tf32 MMA)
    const int smem = (2 * 64 * 68 + 128 * 68) * (int)sizeof(float) + 64;  // 69696
    cudaFuncSetAttribute(attn_tf32_kernel,
                         cudaFuncAttributeMaxDynamicSharedMemorySize, smem);
    attn_tf32_kernel<<<dim3(SS / 128, HH, BB), 256, smem>>>(qkv, mask, att);

    // 3) Output projection
    dim3 g2(FF / 128, MM / 128);     // (6, 64)
    gemm_tf32_kernel<<<g2, 256>>>(att, Wout, bout, out, MM, FF, FF);
}